// round 5
// baseline (speedup 1.0000x reference)
#include <cuda_runtime.h>
#include <cstdint>

#define NQ   22
#define DIM  (1u << NQ)     // 4194304 elements per component

// ---- tiny diagonal split tables (device globals, no allocation) ----
__device__ float g_dLo[2048];
__device__ float g_dHi[2048];
__device__ float g_R[11][2048];

__device__ __forceinline__ void add4(float4& a, const float4 b) {
    a.x += b.x; a.y += b.y; a.z += b.z; a.w += b.w;
}

__device__ __forceinline__ uint32_t smem_u32(const void* p) {
    uint32_t a;
    asm("{ .reg .u64 t; cvta.to.shared.u64 t, %1; cvt.u32.u64 %0, t; }"
        : "=r"(a) : "l"(p));
    return a;
}
__device__ __forceinline__ void cpasync16(uint32_t s, const void* g) {
    asm volatile("cp.async.cg.shared.global [%0], [%1], 16;" :: "r"(s), "l"(g));
}
#define CP_COMMIT() asm volatile("cp.async.commit_group;")
#define CP_WAIT1()  asm volatile("cp.async.wait_group 1;")
#define CP_WAIT0()  asm volatile("cp.async.wait_group 0;")

// ---------------------------------------------------------------------------
// Kernel A: split tables for the diagonal. U staged in smem so the
// accumulation chain is FADD-latency, not LDG-latency.
//   diag[b] = dLo[b&2047] + dHi[b>>11] + sum_{h set in (b>>11)} R[h][b&2047]
// ---------------------------------------------------------------------------
__global__ void __launch_bounds__(128)
tables_kernel(const float* __restrict__ U, const float* __restrict__ detune)
{
    __shared__ float sU[NQ * NQ];
    __shared__ float sdet;
    for (int i = threadIdx.x; i < NQ * NQ; i += 128) sU[i] = U[i];
    if (threadIdx.x == 0) sdet = detune[0];
    __syncthreads();

    const int t = blockIdx.x * 128 + threadIdx.x;   // 0..2047
    const float det = sdet;

    float dlo = 0.f;
#pragma unroll
    for (int p = 0; p < 11; p++) {
        if ((t >> p) & 1) {
            dlo -= det;
#pragma unroll
            for (int q = 0; q < p; q++)
                if ((t >> q) & 1) dlo += sU[(21 - p) * NQ + (21 - q)];
        }
    }
    g_dLo[t] = dlo;

    float dhi = 0.f;
#pragma unroll
    for (int h = 0; h < 11; h++) {
        if ((t >> h) & 1) {
            dhi -= det;
#pragma unroll
            for (int h2 = 0; h2 < h; h2++)
                if ((t >> h2) & 1) dhi += sU[(10 - h) * NQ + (10 - h2)];
        }
    }
    g_dHi[t] = dhi;

#pragma unroll
    for (int h = 0; h < 11; h++) {
        float r = 0.f;
#pragma unroll
        for (int q = 0; q < 11; q++)
            if ((t >> q) & 1) r += sU[(10 - h) * NQ + (21 - q)];
        g_R[h][t] = r;
    }
}

// ---------------------------------------------------------------------------
// Pass A: low bits 0..12 (13 X-neighbors) + diagonal, fused. Persistent CTAs
// (grid 128, exactly 4 tiles each) with cp.async double-buffered 64KB tiles so
// the global fill of tile i+1 overlaps the LDS compute of tile i.
//   tile = 8192 contiguous elements = 2048 float4 groups per component.
//   bits 0..1  : in-float4 register swaps
//   bits 2..10 : 9 smem XOR neighbors on the group index
//   bits 11..12: register exchange across the thread's own k-groups
//   writes out = diag*psi + c*acc_low
// ---------------------------------------------------------------------------
#define A_GRID 128
#define A_TILES 512

__global__ void __launch_bounds__(512)
passA_kernel(const float* __restrict__ sr, const float* __restrict__ si,
             const float* __restrict__ rabi, float* __restrict__ out)
{
    extern __shared__ float4 smem[];   // 2 buffers x (2048 r + 2048 i) = 128KB
    const uint32_t sbase = smem_u32(smem);
    const float4* grp = (const float4*)sr;
    const float4* gip = (const float4*)si;
    float4* outr4 = (float4*)out;
    float4* outi4 = (float4*)(out + DIM);
    const int tid = threadIdx.x;
    const float c = 0.5f * __ldg(rabi);

    // prefetch tile into buffer buf
    auto prefetch = [&](int tile, int buf) {
        const uint32_t b0 = sbase + (uint32_t)buf * 65536u;
        const unsigned gbase = (unsigned)tile * 2048u;
#pragma unroll
        for (int k = 0; k < 4; k++) {
            const int idx = tid + k * 512;
            cpasync16(b0 + idx * 16, grp + gbase + idx);
            cpasync16(b0 + 32768 + idx * 16, gip + gbase + idx);
        }
    };

    int tile = blockIdx.x;
    int buf = 0;
    prefetch(tile, 0);
    CP_COMMIT();

    for (; tile < A_TILES; tile += A_GRID) {
        const int nxt = tile + A_GRID;
        const bool hn = (nxt < A_TILES);
        if (hn) { prefetch(nxt, buf ^ 1); CP_COMMIT(); }
        if (hn) CP_WAIT1(); else CP_WAIT0();
        __syncthreads();

        const float4* smr = smem + buf * 4096;
        const float4* smi = smr + 2048;
        const unsigned chunkG = (unsigned)tile * 2048u;

        float4 vr[4], vi[4];
#pragma unroll
        for (int k = 0; k < 4; k++) {
            const int G = tid + k * 512;
            vr[k] = smr[G];
            vi[k] = smi[G];
        }

#pragma unroll
        for (int k = 0; k < 4; k++) {
            const int G = tid + k * 512;
            const float4 r0 = vr[k], i0 = vi[k];

            // element bit 0: swap within pairs
            float4 ar = make_float4(r0.y, r0.x, r0.w, r0.z);
            float4 ai = make_float4(i0.y, i0.x, i0.w, i0.z);
            // element bit 1: swap halves
            ar.x += r0.z; ar.y += r0.w; ar.z += r0.x; ar.w += r0.y;
            ai.x += i0.z; ai.y += i0.w; ai.z += i0.x; ai.w += i0.y;

            // element bits 11,12 -> group bits 9,10 -> own k^1, k^2 registers
            add4(ar, vr[k ^ 1]); add4(ar, vr[k ^ 2]);
            add4(ai, vi[k ^ 1]); add4(ai, vi[k ^ 2]);

            // element bits 2..10 -> group bits 0..8 via smem
#pragma unroll
            for (int t = 0; t < 9; t++) {
                const int Gn = G ^ (1 << t);
                add4(ar, smr[Gn]);
                add4(ai, smi[Gn]);
            }

            // diagonal from split tables; hi uniform over the 512 threads of k
            const unsigned gG = chunkG + G;
            const unsigned lo = (G << 2) & 2047u;
            const unsigned hi = tile * 4 + k;
            float4 d = *(const float4*)&g_dLo[lo];
            const float dh = g_dHi[hi];
            d.x += dh; d.y += dh; d.z += dh; d.w += dh;
#pragma unroll
            for (int h = 0; h < 11; h++) {
                if ((hi >> h) & 1) {
                    const float4 rr = *(const float4*)&g_R[h][lo];
                    add4(d, rr);
                }
            }

            float4 o;
            o.x = fmaf(d.x, r0.x, c * ar.x);
            o.y = fmaf(d.y, r0.y, c * ar.y);
            o.z = fmaf(d.z, r0.z, c * ar.z);
            o.w = fmaf(d.w, r0.w, c * ar.w);
            outr4[gG] = o;
            float4 p;
            p.x = fmaf(d.x, i0.x, c * ai.x);
            p.y = fmaf(d.y, i0.y, c * ai.y);
            p.z = fmaf(d.z, i0.z, c * ai.z);
            p.w = fmaf(d.w, i0.w, c * ai.w);
            outi4[gG] = p;
        }
        __syncthreads();   // buffer reuse guard
        buf ^= 1;
    }
}

// ---------------------------------------------------------------------------
// Pass B: high bits 13..21 (9 X-neighbors), retiled; persistent + double
// buffered like pass A. Tile = 512 high-combos (bits 13..21) x 16 consecutive
// elements (bits 0..3); tile index mid = element bits 4..12 (512 tiles).
//   smem float4 index idx = combo*4 + rf4  (rf4 = bits 2..3 of element).
//   neighbors: idx ^ (4<<t), t=0..8. RMW: out += c*acc_high.
// ---------------------------------------------------------------------------
#define B_GRID 128
#define B_TILES 512

__global__ void __launch_bounds__(512)
passB_kernel(const float* __restrict__ sr, const float* __restrict__ si,
             const float* __restrict__ rabi, float* __restrict__ out)
{
    extern __shared__ float4 smem[];   // 2 buffers x (2048 r + 2048 i) = 128KB
    const uint32_t sbase = smem_u32(smem);
    const float4* grp = (const float4*)sr;
    const float4* gip = (const float4*)si;
    float4* outr4 = (float4*)out;
    float4* outi4 = (float4*)(out + DIM);
    const int tid = threadIdx.x;
    const float c = 0.5f * __ldg(rabi);

    auto gidx = [&](int mid, int idx) -> unsigned {
        const unsigned combo = (unsigned)idx >> 2;
        const unsigned rf4 = (unsigned)idx & 3u;
        return (combo << 11) + ((unsigned)mid << 2) + rf4;
    };

    auto prefetch = [&](int mid, int buf) {
        const uint32_t b0 = sbase + (uint32_t)buf * 65536u;
#pragma unroll
        for (int k = 0; k < 4; k++) {
            const int idx = tid + k * 512;
            const unsigned gG = gidx(mid, idx);
            cpasync16(b0 + idx * 16, grp + gG);
            cpasync16(b0 + 32768 + idx * 16, gip + gG);
        }
    };

    int mid = blockIdx.x;
    int buf = 0;
    prefetch(mid, 0);
    CP_COMMIT();

    for (; mid < B_TILES; mid += B_GRID) {
        const int nxt = mid + B_GRID;
        const bool hn = (nxt < B_TILES);
        if (hn) { prefetch(nxt, buf ^ 1); CP_COMMIT(); }
        if (hn) CP_WAIT1(); else CP_WAIT0();
        __syncthreads();

        const float4* smr = smem + buf * 4096;
        const float4* smi = smr + 2048;

#pragma unroll
        for (int k = 0; k < 4; k++) {
            const int idx = tid + k * 512;
            float4 ar = make_float4(0.f, 0.f, 0.f, 0.f);
            float4 ai = make_float4(0.f, 0.f, 0.f, 0.f);
#pragma unroll
            for (int t = 0; t < 9; t++) {
                const int n = idx ^ (4 << t);   // flip elem bit 13+t
                add4(ar, smr[n]);
                add4(ai, smi[n]);
            }
            const unsigned gG = gidx(mid, idx);
            float4 o = outr4[gG];
            o.x = fmaf(c, ar.x, o.x);
            o.y = fmaf(c, ar.y, o.y);
            o.z = fmaf(c, ar.z, o.z);
            o.w = fmaf(c, ar.w, o.w);
            outr4[gG] = o;
            float4 p = outi4[gG];
            p.x = fmaf(c, ai.x, p.x);
            p.y = fmaf(c, ai.y, p.y);
            p.z = fmaf(c, ai.z, p.z);
            p.w = fmaf(c, ai.w, p.w);
            outi4[gG] = p;
        }
        __syncthreads();   // buffer reuse guard
        buf ^= 1;
    }
}

// ---------------------------------------------------------------------------
// Launch: tables -> passA (low + diag, writes out) -> passB (high, RMW out).
// ---------------------------------------------------------------------------
extern "C" void kernel_launch(void* const* d_in, const int* in_sizes, int n_in,
                              void* d_out, int out_size)
{
    const float* sr     = (const float*)d_in[0];
    const float* si     = (const float*)d_in[1];
    const float* rabi   = (const float*)d_in[2];
    const float* detune = (const float*)d_in[3];
    const float* U      = (const float*)d_in[4];
    float* out = (float*)d_out;

    cudaFuncSetAttribute(passA_kernel,
                         cudaFuncAttributeMaxDynamicSharedMemorySize, 131072);
    cudaFuncSetAttribute(passB_kernel,
                         cudaFuncAttributeMaxDynamicSharedMemorySize, 131072);

    tables_kernel<<<16, 128>>>(U, detune);
    passA_kernel<<<A_GRID, 512, 131072>>>(sr, si, rabi, out);
    passB_kernel<<<B_GRID, 512, 131072>>>(sr, si, rabi, out);
}

// round 6
// speedup vs baseline: 1.0437x; 1.0437x over previous
#include <cuda_runtime.h>
#include <cstdint>

#define NQ   22
#define DIM  (1u << NQ)     // 4194304 elements per component

// ---- tiny diagonal split tables (device globals, no allocation) ----
// diag[b] = dLo[b&2047] + dHi[b>>11] + sum_{h set in (b>>11)} R[h][b&2047]
__device__ float g_dLo[2048];
__device__ float g_dHi[2048];
__device__ float g_R[11][2048];

__device__ __forceinline__ void add4(float4& a, const float4 b) {
    a.x += b.x; a.y += b.y; a.z += b.z; a.w += b.w;
}
__device__ __forceinline__ float4 sum4(const float4 a, const float4 b) {
    return make_float4(a.x + b.x, a.y + b.y, a.z + b.z, a.w + b.w);
}

__device__ __forceinline__ uint32_t smem_u32(const void* p) {
    uint32_t a;
    asm("{ .reg .u64 t; cvta.to.shared.u64 t, %1; cvt.u32.u64 %0, t; }"
        : "=r"(a) : "l"(p));
    return a;
}
__device__ __forceinline__ void cpasync16(uint32_t s, const void* g) {
    asm volatile("cp.async.cg.shared.global [%0], [%1], 16;" :: "r"(s), "l"(g));
}
#define CP_COMMIT() asm volatile("cp.async.commit_group;")
#define CP_WAIT1()  asm volatile("cp.async.wait_group 1;")
#define CP_WAIT0()  asm volatile("cp.async.wait_group 0;")

// ---------------------------------------------------------------------------
// Table computation, inlined into K1 (CTAs 0..7, 256 entries each).
// U staged through smem so chains are FADD-latency.
// ---------------------------------------------------------------------------
__device__ void compute_tables(const float* __restrict__ U,
                               const float* __restrict__ detune,
                               float* sU /* >= 485 floats of smem */)
{
    for (int i = threadIdx.x; i < NQ * NQ; i += 256) sU[i] = U[i];
    if (threadIdx.x == 0) sU[NQ * NQ] = detune[0];
    __syncthreads();
    const float det = sU[NQ * NQ];
    const int t = blockIdx.x * 256 + threadIdx.x;   // 0..2047

    float dlo = 0.f;
#pragma unroll
    for (int p = 0; p < 11; p++) {
        if ((t >> p) & 1) {
            dlo -= det;
#pragma unroll
            for (int q = 0; q < p; q++)
                if ((t >> q) & 1) dlo += sU[(21 - p) * NQ + (21 - q)];
        }
    }
    g_dLo[t] = dlo;

    float dhi = 0.f;
#pragma unroll
    for (int h = 0; h < 11; h++) {
        if ((t >> h) & 1) {
            dhi -= det;
#pragma unroll
            for (int h2 = 0; h2 < h; h2++)
                if ((t >> h2) & 1) dhi += sU[(10 - h) * NQ + (10 - h2)];
        }
    }
    g_dHi[t] = dhi;

#pragma unroll
    for (int h = 0; h < 11; h++) {
        float r = 0.f;
#pragma unroll
        for (int q = 0; q < 11; q++)
            if ((t >> q) & 1) r += sU[(10 - h) * NQ + (21 - q)];
        g_R[h][t] = r;
    }
    __syncthreads();
}

// ---------------------------------------------------------------------------
// K1: low bits 0..12 (13 X-neighbors), NO diag. Also computes the diag
// tables (CTAs 0..7) for K2. Persistent grid 128 x 4 tiles, double-buffered
// cp.async 64KB tiles.
//   tile = 8192 consecutive elements = 2048 float4 groups per component
//   thread owns 8 groups: G = tid + k*256  (k = G bits 8..10 = elem bits 10..12)
//   bits 0..1  : in-float4 register swaps
//   bits 2..9  : 8 smem XOR neighbors on G bits 0..7
//   bits 10..12: register exchange k^1, k^2, k^4
//   writes out = c * acc_low
// ---------------------------------------------------------------------------
__global__ void __launch_bounds__(256)
k1_low_kernel(const float* __restrict__ sr, const float* __restrict__ si,
              const float* __restrict__ rabi, float* __restrict__ out,
              const float* __restrict__ U, const float* __restrict__ detune)
{
    extern __shared__ float4 smem[];   // 2 x (2048 r + 2048 i) float4 = 128KB
    __shared__ float sU[NQ * NQ + 1];
    const uint32_t sbase = smem_u32(smem);
    const float4* grp = (const float4*)sr;
    const float4* gip = (const float4*)si;
    float4* outr4 = (float4*)out;
    float4* outi4 = (float4*)(out + DIM);
    const int tid = threadIdx.x;
    const float c = 0.5f * __ldg(rabi);

    auto prefetch = [&](int tile, int buf) {
        const uint32_t b0 = sbase + (uint32_t)buf * 65536u;
        const unsigned gbase = (unsigned)tile << 11;
#pragma unroll
        for (int k = 0; k < 8; k++) {
            const int G = tid + k * 256;
            cpasync16(b0 + G * 16, grp + gbase + G);
            cpasync16(b0 + 32768 + G * 16, gip + gbase + G);
        }
    };

    int tile = blockIdx.x;
    prefetch(tile, 0);
    CP_COMMIT();

    // CTAs 0..7 compute the diag tables for K2 while their first fill flies.
    if (blockIdx.x < 8) compute_tables(U, detune, sU);

    int buf = 0;
    for (; tile < 512; tile += 128) {
        const bool hn = (tile + 128 < 512);
        if (hn) { prefetch(tile + 128, buf ^ 1); CP_COMMIT(); }
        if (hn) CP_WAIT1(); else CP_WAIT0();
        __syncthreads();

        const float4* smr = smem + buf * 4096;
        const float4* smi = smr + 2048;
        const unsigned chunkG = (unsigned)tile << 11;

        float4 vr[8], vi[8];
#pragma unroll
        for (int k = 0; k < 8; k++) {
            const int G = tid + k * 256;
            vr[k] = smr[G];
            vi[k] = smi[G];
        }

#pragma unroll
        for (int k = 0; k < 8; k++) {
            const int G = tid + k * 256;
            const float4 r0 = vr[k], i0 = vi[k];

            // elem bit 0: swap within pairs
            float4 ar = make_float4(r0.y, r0.x, r0.w, r0.z);
            float4 ai = make_float4(i0.y, i0.x, i0.w, i0.z);
            // elem bit 1: swap halves
            ar.x += r0.z; ar.y += r0.w; ar.z += r0.x; ar.w += r0.y;
            ai.x += i0.z; ai.y += i0.w; ai.z += i0.x; ai.w += i0.y;

            // elem bits 10..12 : register sub-cube
            add4(ar, vr[k ^ 1]); add4(ar, vr[k ^ 2]); add4(ar, vr[k ^ 4]);
            add4(ai, vi[k ^ 1]); add4(ai, vi[k ^ 2]); add4(ai, vi[k ^ 4]);

            // elem bits 2..9 : smem XOR neighbors
#pragma unroll
            for (int t = 0; t < 8; t++) {
                const int Gn = G ^ (1 << t);
                add4(ar, smr[Gn]);
                add4(ai, smi[Gn]);
            }

            const unsigned gG = chunkG + G;
            outr4[gG] = make_float4(c * ar.x, c * ar.y, c * ar.z, c * ar.w);
            outi4[gG] = make_float4(c * ai.x, c * ai.y, c * ai.z, c * ai.w);
        }
        __syncthreads();   // buffer reuse guard
        buf ^= 1;
    }
}

// ---------------------------------------------------------------------------
// K2: high bits 13..21 (9 X-neighbors) + diagonal, RMW into out.
//   tile: mid = elem bits 4..12 (512 tiles); inside: combo = bits 13..21
//   (512 values) x 16 consecutive elements (bits 0..3).
//   smem float4 index idx = combo*4 + rf4, rf4 = bits 2..3.
//   thread owns 8 groups: idx = tid + k*256 -> combo = (tid>>2) + k*64
//   bits 13..18: 6 smem XOR neighbors (combo bits 0..5)
//   bits 19..21: register exchange k^1, k^2, k^4
//   diag: per-thread lo-float4 is FIXED (tid&3) -> stage base cross term
//   once per tile; k-dependent part via an 8-entry subset-sum of 3 R rows.
//   out += c*acc_high + diag .* psi
// ---------------------------------------------------------------------------
__global__ void __launch_bounds__(256)
k2_high_kernel(const float* __restrict__ sr, const float* __restrict__ si,
               const float* __restrict__ rabi, float* __restrict__ out)
{
    extern __shared__ float4 smem[];   // 2 x (2048 r + 2048 i) float4 = 128KB
    const uint32_t sbase = smem_u32(smem);
    const float4* grp = (const float4*)sr;
    const float4* gip = (const float4*)si;
    float4* outr4 = (float4*)out;
    float4* outi4 = (float4*)(out + DIM);
    const int tid = threadIdx.x;
    const float c = 0.5f * __ldg(rabi);

    const int cb6 = (tid >> 2) & 63;   // combo bits 0..5 (fixed per thread)
    const int rf4 = tid & 3;           // float4-within-row (fixed per thread)

    auto prefetch = [&](int mid, int buf) {
        const uint32_t b0 = sbase + (uint32_t)buf * 65536u;
#pragma unroll
        for (int k = 0; k < 8; k++) {
            const int idx = tid + k * 256;
            const unsigned gG = ((unsigned)(idx >> 2) << 11) + ((unsigned)mid << 2) + (idx & 3);
            cpasync16(b0 + idx * 16, grp + gG);
            cpasync16(b0 + 32768 + idx * 16, gip + gG);
        }
    };

    int mid = blockIdx.x;
    prefetch(mid, 0);
    CP_COMMIT();

    int buf = 0;
    for (; mid < 512; mid += 128) {
        const bool hn = (mid + 128 < 512);
        if (hn) { prefetch(mid + 128, buf ^ 1); CP_COMMIT(); }

        // ---- per-tile diag precompute (L1-resident tables, no smem) ----
        const int lo4 = ((mid & 127) << 4) | (rf4 << 2);  // lo of float4 base
        const int midhi = mid >> 7;                        // hi bits 0..1
        float4 base4 = __ldg((const float4*)&g_dLo[lo4]);
        if (midhi & 1) add4(base4, __ldg((const float4*)&g_R[0][lo4]));
        if (midhi & 2) add4(base4, __ldg((const float4*)&g_R[1][lo4]));
#pragma unroll
        for (int t = 0; t < 6; t++)
            if ((cb6 >> t) & 1) add4(base4, __ldg((const float4*)&g_R[t + 2][lo4]));
        const float4 r8  = __ldg((const float4*)&g_R[8][lo4]);
        const float4 r9  = __ldg((const float4*)&g_R[9][lo4]);
        const float4 r10 = __ldg((const float4*)&g_R[10][lo4]);
        float4 kc[8];
        kc[0] = make_float4(0.f, 0.f, 0.f, 0.f);
        kc[1] = r8;
        kc[2] = r9;
        kc[3] = sum4(r8, r9);
        kc[4] = r10;
        kc[5] = sum4(r8, r10);
        kc[6] = sum4(r9, r10);
        kc[7] = sum4(kc[3], r10);

        if (hn) CP_WAIT1(); else CP_WAIT0();
        __syncthreads();

        const float4* smr = smem + buf * 4096;
        const float4* smi = smr + 2048;

        float4 vr[8], vi[8];
#pragma unroll
        for (int k = 0; k < 8; k++) {
            const int idx = tid + k * 256;
            vr[k] = smr[idx];
            vi[k] = smi[idx];
        }

#pragma unroll
        for (int k = 0; k < 8; k++) {
            const int idx = tid + k * 256;

            // elem bits 19..21 : register sub-cube
            float4 ar = sum4(vr[k ^ 1], vr[k ^ 2]);
            float4 ai = sum4(vi[k ^ 1], vi[k ^ 2]);
            add4(ar, vr[k ^ 4]);
            add4(ai, vi[k ^ 4]);

            // elem bits 13..18 : smem XOR neighbors
#pragma unroll
            for (int t = 0; t < 6; t++) {
                const int n = idx ^ (4 << t);
                add4(ar, smr[n]);
                add4(ai, smi[n]);
            }

            // diagonal for this group (hi = combo<<2 | midhi)
            const int combo = cb6 + k * 64;
            const float dh = __ldg(&g_dHi[(combo << 2) | midhi]);
            float4 W = sum4(base4, kc[k]);
            W.x += dh; W.y += dh; W.z += dh; W.w += dh;

            const unsigned gG = ((unsigned)combo << 11) + ((unsigned)mid << 2) + rf4;
            float4 o = outr4[gG];
            o.x = fmaf(c, ar.x, fmaf(W.x, vr[k].x, o.x));
            o.y = fmaf(c, ar.y, fmaf(W.y, vr[k].y, o.y));
            o.z = fmaf(c, ar.z, fmaf(W.z, vr[k].z, o.z));
            o.w = fmaf(c, ar.w, fmaf(W.w, vr[k].w, o.w));
            outr4[gG] = o;
            float4 p = outi4[gG];
            p.x = fmaf(c, ai.x, fmaf(W.x, vi[k].x, p.x));
            p.y = fmaf(c, ai.y, fmaf(W.y, vi[k].y, p.y));
            p.z = fmaf(c, ai.z, fmaf(W.z, vi[k].z, p.z));
            p.w = fmaf(c, ai.w, fmaf(W.w, vi[k].w, p.w));
            outi4[gG] = p;
        }
        __syncthreads();   // buffer reuse guard
        buf ^= 1;
    }
}

// ---------------------------------------------------------------------------
// Launch: K1 (low dirs + tables) -> K2 (high dirs + diag, RMW).
// ---------------------------------------------------------------------------
extern "C" void kernel_launch(void* const* d_in, const int* in_sizes, int n_in,
                              void* d_out, int out_size)
{
    const float* sr     = (const float*)d_in[0];
    const float* si     = (const float*)d_in[1];
    const float* rabi   = (const float*)d_in[2];
    const float* detune = (const float*)d_in[3];
    const float* U      = (const float*)d_in[4];
    float* out = (float*)d_out;

    cudaFuncSetAttribute(k1_low_kernel,
                         cudaFuncAttributeMaxDynamicSharedMemorySize, 131072);
    cudaFuncSetAttribute(k2_high_kernel,
                         cudaFuncAttributeMaxDynamicSharedMemorySize, 131072);

    k1_low_kernel<<<128, 256, 131072>>>(sr, si, rabi, out, U, detune);
    k2_high_kernel<<<128, 256, 131072>>>(sr, si, rabi, out);
}

// round 7
// speedup vs baseline: 1.2097x; 1.1590x over previous
#include <cuda_runtime.h>
#include <cstdint>

#define NQ   22
#define DIM  (1u << NQ)     // 4194304 elements per component

// ---- tiny diagonal split tables (device globals, no allocation) ----
// diag[b] = dLo[b&2047] + dHi[b>>11] + sum_{h set in (b>>11)} R[h][b&2047]
__device__ float g_dLo[2048];
__device__ float g_dHi[2048];
__device__ float g_R[11][2048];

__device__ __forceinline__ void add4(float4& a, const float4 b) {
    a.x += b.x; a.y += b.y; a.z += b.z; a.w += b.w;
}

__device__ __forceinline__ uint32_t smem_u32(const void* p) {
    uint32_t a;
    asm("{ .reg .u64 t; cvta.to.shared.u64 t, %1; cvt.u32.u64 %0, t; }"
        : "=r"(a) : "l"(p));
    return a;
}
__device__ __forceinline__ void cpasync16(uint32_t s, const void* g) {
    asm volatile("cp.async.cg.shared.global [%0], [%1], 16;" :: "r"(s), "l"(g));
}
#define CP_COMMIT() asm volatile("cp.async.commit_group;")
#define CP_WAIT0()  asm volatile("cp.async.wait_group 0;")

// ---------------------------------------------------------------------------
// Diag tables, computed by K1 CTAs 0..3 (512 entries each), read only by K2.
// U staged in smem so the chains are FADD-latency.
// ---------------------------------------------------------------------------
__device__ void compute_tables(const float* __restrict__ U,
                               const float* __restrict__ detune,
                               float* sU /* >= 485 floats */)
{
    for (int i = threadIdx.x; i < NQ * NQ; i += 512) sU[i] = U[i];
    if (threadIdx.x == 0) sU[NQ * NQ] = detune[0];
    __syncthreads();
    const float det = sU[NQ * NQ];
    const int t = blockIdx.x * 512 + threadIdx.x;   // 0..2047

    float dlo = 0.f;
#pragma unroll
    for (int p = 0; p < 11; p++) {
        if ((t >> p) & 1) {
            dlo -= det;
#pragma unroll
            for (int q = 0; q < p; q++)
                if ((t >> q) & 1) dlo += sU[(21 - p) * NQ + (21 - q)];
        }
    }
    g_dLo[t] = dlo;

    float dhi = 0.f;
#pragma unroll
    for (int h = 0; h < 11; h++) {
        if ((t >> h) & 1) {
            dhi -= det;
#pragma unroll
            for (int h2 = 0; h2 < h; h2++)
                if ((t >> h2) & 1) dhi += sU[(10 - h) * NQ + (10 - h2)];
        }
    }
    g_dHi[t] = dhi;

#pragma unroll
    for (int h = 0; h < 11; h++) {
        float r = 0.f;
#pragma unroll
        for (int q = 0; q < 11; q++)
            if ((t >> q) & 1) r += sU[(10 - h) * NQ + (21 - q)];
        g_R[h][t] = r;
    }
}

// ---------------------------------------------------------------------------
// K1: low bits 0..12 (13 X-neighbors), writes out = c*acc. No diag.
//   One 64KB tile (8192 consecutive elems) per CTA, grid 512, 512 threads,
//   2 CTAs/SM. Thread owns 4 f4-groups: G = tid + k*512.
//   bits 0..1  : in-float4 swaps
//   bits 2..10 : 9 smem XOR dirs on G bits 0..8 (tid)
//   bits 11..12: register dirs k^1, k^2
//   Components processed sequentially to keep registers ~45.
//   CTAs 0..3 also compute the diag tables (for K2) while their fill flies.
// ---------------------------------------------------------------------------
__global__ void __launch_bounds__(512, 2)
k1_low_kernel(const float* __restrict__ sr, const float* __restrict__ si,
              const float* __restrict__ rabi, float* __restrict__ out,
              const float* __restrict__ U, const float* __restrict__ detune)
{
    extern __shared__ float4 smem[];   // [2048 r][2048 i] = 64KB
    __shared__ float sU[NQ * NQ + 1];
    const uint32_t sb = smem_u32(smem);
    const int tid = threadIdx.x;
    const unsigned gbase = (unsigned)blockIdx.x << 11;   // f4-group base
    const float4* grp = (const float4*)sr;
    const float4* gip = (const float4*)si;

#pragma unroll
    for (int j = 0; j < 4; j++) {
        const int idx = tid + j * 512;
        cpasync16(sb + idx * 16, grp + gbase + idx);
        cpasync16(sb + 32768 + idx * 16, gip + gbase + idx);
    }
    CP_COMMIT();
    const float c = 0.5f * __ldg(rabi);

    if (blockIdx.x < 4) compute_tables(U, detune, sU);

    CP_WAIT0();
    __syncthreads();

#pragma unroll
    for (int comp = 0; comp < 2; comp++) {
        const float4* sv = smem + comp * 2048;
        float4* o4 = (float4*)(out + comp * DIM);

        float4 v[4];
#pragma unroll
        for (int k = 0; k < 4; k++) v[k] = sv[tid + k * 512];

#pragma unroll
        for (int k = 0; k < 4; k++) {
            const int G = tid + k * 512;
            const float4 s = v[k];
            // elem bit 0: swap within pairs; elem bit 1: swap halves
            float4 a = make_float4(s.y + s.z, s.x + s.w, s.w + s.x, s.z + s.y);
            // elem bits 11..12: register dirs
            add4(a, v[k ^ 1]);
            add4(a, v[k ^ 2]);
            // elem bits 2..10: smem dirs
#pragma unroll
            for (int t = 0; t < 9; t++)
                add4(a, sv[G ^ (1 << t)]);

            o4[gbase + G] = make_float4(c * a.x, c * a.y, c * a.z, c * a.w);
        }
    }
}

// ---------------------------------------------------------------------------
// K2: high bits 13..21 (9 X-neighbors) + diagonal, RMW into out.
//   mid = elem bits 4..12 (grid 512). Tile: 512 combos (bits 13..21) x 16
//   consecutive elems (bits 0..3); f4 index idx = combo*4 + rf4.
//   Thread owns idx = tid + k*512: rf4 = tid&3, combo bits 0..6 = tid>>2,
//   combo bits 7..8 = k.
//   bits 13..19: 7 smem XOR dirs; bits 20..21: register dirs k^1, k^2.
//   diag: lo-f4 fixed per thread -> base4 staged via L1 LDGs; k-part is
//   unrolled-constant adds of R[9]/R[10]; dHi scalar per k.
//   out += c*acc + diag .* psi
// ---------------------------------------------------------------------------
__global__ void __launch_bounds__(512, 2)
k2_high_kernel(const float* __restrict__ sr, const float* __restrict__ si,
               const float* __restrict__ rabi, float* __restrict__ out)
{
    extern __shared__ float4 smem[];   // [2048 r][2048 i] = 64KB
    const uint32_t sb = smem_u32(smem);
    const int tid = threadIdx.x;
    const unsigned mid = blockIdx.x;               // elem bits 4..12
    const int rf4 = tid & 3;
    const int cb7 = tid >> 2;                      // combo bits 0..6
    const float4* grp = (const float4*)sr;
    const float4* gip = (const float4*)si;

#pragma unroll
    for (int j = 0; j < 4; j++) {
        const int idx = tid + j * 512;
        const unsigned gG = ((unsigned)(idx >> 2) << 11) + (mid << 2) + (idx & 3);
        cpasync16(sb + idx * 16, grp + gG);
        cpasync16(sb + 32768 + idx * 16, gip + gG);
    }
    CP_COMMIT();
    const float c = 0.5f * __ldg(rabi);

    // ---- diag staging (L1 loads; overlaps the cp.async fill) ----
    const int lo4 = ((int)(mid & 127u) << 4) | (rf4 << 2);
    const int midhi = (int)(mid >> 7);             // elem bits 11..12 = hi bits 0..1
    float4 base4 = __ldg((const float4*)&g_dLo[lo4]);
    if (midhi & 1) add4(base4, __ldg((const float4*)&g_R[0][lo4]));
    if (midhi & 2) add4(base4, __ldg((const float4*)&g_R[1][lo4]));
#pragma unroll
    for (int t = 0; t < 7; t++)
        if ((cb7 >> t) & 1) add4(base4, __ldg((const float4*)&g_R[t + 2][lo4]));
    const float4 r9  = __ldg((const float4*)&g_R[9][lo4]);
    const float4 r10 = __ldg((const float4*)&g_R[10][lo4]);
    float dh[4];
#pragma unroll
    for (int k = 0; k < 4; k++)
        dh[k] = __ldg(&g_dHi[(((unsigned)(cb7 | (k << 7)) << 2) | midhi)]);

    CP_WAIT0();
    __syncthreads();

#pragma unroll
    for (int comp = 0; comp < 2; comp++) {
        const float4* sv = smem + comp * 2048;
        float4* o4 = (float4*)(out + comp * DIM);

        float4 v[4];
#pragma unroll
        for (int k = 0; k < 4; k++) v[k] = sv[tid + k * 512];

#pragma unroll
        for (int k = 0; k < 4; k++) {
            const int idx = tid + k * 512;
            // elem bits 20..21: register dirs
            float4 a = v[k ^ 1];
            add4(a, v[k ^ 2]);
            // elem bits 13..19: smem dirs on combo bits 0..6
#pragma unroll
            for (int t = 0; t < 7; t++)
                add4(a, sv[idx ^ (4 << t)]);

            // diagonal weight for this group
            float4 W = base4;
            if (k & 1) add4(W, r9);
            if (k & 2) add4(W, r10);
            W.x += dh[k]; W.y += dh[k]; W.z += dh[k]; W.w += dh[k];

            const unsigned gG = ((unsigned)(idx >> 2) << 11) + (mid << 2) + (idx & 3);
            float4 o = o4[gG];
            o.x = fmaf(c, a.x, fmaf(W.x, v[k].x, o.x));
            o.y = fmaf(c, a.y, fmaf(W.y, v[k].y, o.y));
            o.z = fmaf(c, a.z, fmaf(W.z, v[k].z, o.z));
            o.w = fmaf(c, a.w, fmaf(W.w, v[k].w, o.w));
            o4[gG] = o;
        }
    }
}

// ---------------------------------------------------------------------------
// Launch: K1 (low dirs, writes out; CTAs 0..3 build tables)
//      -> K2 (high dirs + diag, RMW out).
// ---------------------------------------------------------------------------
extern "C" void kernel_launch(void* const* d_in, const int* in_sizes, int n_in,
                              void* d_out, int out_size)
{
    const float* sr     = (const float*)d_in[0];
    const float* si     = (const float*)d_in[1];
    const float* rabi   = (const float*)d_in[2];
    const float* detune = (const float*)d_in[3];
    const float* U      = (const float*)d_in[4];
    float* out = (float*)d_out;

    cudaFuncSetAttribute(k1_low_kernel,
                         cudaFuncAttributeMaxDynamicSharedMemorySize, 65536);
    cudaFuncSetAttribute(k2_high_kernel,
                         cudaFuncAttributeMaxDynamicSharedMemorySize, 65536);

    k1_low_kernel<<<512, 512, 65536>>>(sr, si, rabi, out, U, detune);
    k2_high_kernel<<<512, 512, 65536>>>(sr, si, rabi, out);
}